// round 12
// baseline (speedup 1.0000x reference)
#include <cuda_runtime.h>
#include <cuda_bf16.h>
#include <cstdint>

#define D_DIM   20000
#define KOUT    64
#define BATCH   4096
#define BINS    10
#define NCHUNK  1250            /* D_DIM / 16 */
#define KSPLIT  25
#define CPS     50              /* chunks per K segment (50*16 = 800) */

#define Y_OFF   0
#define DISC_OFF (BATCH * KOUT)            /* 262144 */
#define TEMP_OFF (DISC_OFF + KOUT * D_DIM) /* 1542144 */

/* ------------------------- scratch (device globals) ------------------------- */
__device__ float          g_W[KOUT * D_DIM];                 /* (logits+gumbel)/t  */
__device__ float          g_max[D_DIM];
__device__ float          g_logden[D_DIM];
__device__ __nv_bfloat16  g_SB[(size_t)NCHUNK * 4 * KOUT * 8]; /* packed S hi/lo   */
__device__ float          g_candV[KOUT * KOUT];
__device__ int            g_candC[KOUT * KOUT];
__device__ int            g_assign[KOUT];
__device__ float          g_part[(size_t)KSPLIT * BATCH * KOUT];

/* ------------------------------- threefry ---------------------------------- */
/* JAX threefry2x32 with key = threefry_seed(42) = (0, 42). */
__device__ __forceinline__ void threefry2x32(unsigned c0, unsigned c1,
                                             unsigned &o0, unsigned &o1) {
    const unsigned k0 = 0u, k1 = 42u, k2 = 0x1BD11BF0u; /* 0x1BD11BDA^0^42 */
    unsigned x0 = c0 + k0, x1 = c1 + k1;
#define TFR(r) { x0 += x1; x1 = (x1 << r) | (x1 >> (32 - r)); x1 ^= x0; }
    TFR(13) TFR(15) TFR(26) TFR(6)   x0 += k1; x1 += k2 + 1u;
    TFR(17) TFR(29) TFR(16) TFR(24)  x0 += k2; x1 += k0 + 2u;
    TFR(13) TFR(15) TFR(26) TFR(6)   x0 += k0; x1 += k1 + 3u;
    TFR(17) TFR(29) TFR(16) TFR(24)  x0 += k1; x1 += k2 + 4u;
    TFR(13) TFR(15) TFR(26) TFR(6)   x0 += k2; x1 += k0 + 5u;
#undef TFR
    o0 = x0; o1 = x1;
}

/* jax_threefry_partitionable 32-bit path: counter (0, i), bits = o0 ^ o1. */
__device__ __forceinline__ float gumbel_at(unsigned flat) {
    unsigned o0, o1;
    threefry2x32(0u, flat, o0, o1);
    unsigned bits = o0 ^ o1;
    float f   = __uint_as_float((bits >> 9) | 0x3f800000u) - 1.0f; /* [0,1) */
    float val = f * (1.0f - 1e-7f) + 1e-7f;
    val = fmaxf(1e-7f, val);
    return -logf(-logf(val));
}

/* ------- kernel A1: per-d softmax max & log-denominator (warp per d) -------- */
__global__ void kA1_denom(const float* __restrict__ u,
                          const float* __restrict__ tw) {
    __shared__ float stw[BINS * KOUT];
    int tid = threadIdx.x;
    for (int i = tid; i < BINS * KOUT; i += blockDim.x) stw[i] = tw[i];
    __syncthreads();

    int gw = (blockIdx.x * blockDim.x + tid) >> 5;
    int lane = tid & 31;
    if (gw >= D_DIM) return;
    int d = gw;

    float uv[BINS];
#pragma unroll
    for (int j = 0; j < BINS; j++) uv[j] = u[(size_t)d * BINS + j];

    float d0 = 0.f, d1 = 0.f;
#pragma unroll
    for (int j = 0; j < BINS; j++) {
        d0 += uv[j] * stw[j * KOUT + lane];
        d1 += uv[j] * stw[j * KOUT + lane + 32];
    }
    float m = fmaxf(d0, d1);
#pragma unroll
    for (int off = 16; off; off >>= 1) m = fmaxf(m, __shfl_xor_sync(0xffffffffu, m, off));
    float s = expf(d0 - m) + expf(d1 - m);
#pragma unroll
    for (int off = 16; off; off >>= 1) s += __shfl_xor_sync(0xffffffffu, s, off);
    if (lane == 0) { g_max[d] = m; g_logden[d] = logf(s); }
}

/* ---------- kernel A2: W[k][d] = (log(10*clip(al)) + gumbel)/t -------------
   log(10*clip(al)) = log(10) + clamp(dot - m - logden, log(eps), log(1-1e-7)) */
__global__ void kA2_compute_w(const float* __restrict__ u,
                              const float* __restrict__ tw,
                              const float* __restrict__ temp) {
    int idx = blockIdx.x * blockDim.x + threadIdx.x;
    if (idx >= KOUT * D_DIM) return;
    int k = idx / D_DIM;
    int d = idx - k * D_DIM;

    float dot = 0.f;
#pragma unroll
    for (int j = 0; j < BINS; j++)
        dot += u[(size_t)d * BINS + j] * __ldg(&tw[j * KOUT + k]);

    float t = dot - g_max[d] - g_logden[d];             /* = log(al) */
    t = fminf(fmaxf(t, -16.11809565f), -1.0000000e-7f); /* log clip  */
    float lg = 2.302585093f + t;                        /* log(10*al)*/
    float g  = gumbel_at((unsigned)idx);                /* flat = k*D+d */
    float nt = fmaxf(0.1f, temp[0] * 0.99999f);
    g_W[idx] = (lg + g) / nt;
}

/* ------- kernel B: row softmax + packed bf16 hi/lo S + per-row top-64 ------- */
__global__ void kB_rowsoftmax() {
    extern __shared__ float row[];             /* 20000 floats = 80000 B */
    __shared__ float red[256];
    __shared__ unsigned long long wbest[8];
    __shared__ unsigned long long sbest;

    int n = blockIdx.x, tid = threadIdx.x;
    int wid = tid >> 5, lane = tid & 31;
    const float* Wrow = g_W + (size_t)n * D_DIM;

    float m = -1e30f;
    for (int i = tid; i < D_DIM; i += 256) { float v = Wrow[i]; row[i] = v; m = fmaxf(m, v); }
    red[tid] = m; __syncthreads();
    for (int s = 128; s > 0; s >>= 1) { if (tid < s) red[tid] = fmaxf(red[tid], red[tid + s]); __syncthreads(); }
    m = red[0]; __syncthreads();

    float ps = 0.f;
    for (int i = tid; i < D_DIM; i += 256) { float e = expf(row[i] - m); row[i] = e; ps += e; }
    red[tid] = ps; __syncthreads();
    for (int s = 128; s > 0; s >>= 1) { if (tid < s) red[tid] += red[tid + s]; __syncthreads(); }
    float inv = 1.0f / red[0]; __syncthreads();

    /* normalize + pack hi/lo bf16 (mma B-fragment order) + build top-4 cache */
    unsigned long long c0 = 0, c1 = 0, c2 = 0, c3 = 0;
    for (int i = tid; i < D_DIM; i += 256) {
        float v = row[i] * inv;
        row[i] = v;
        __nv_bfloat16 h = __float2bfloat16(v);
        float hf = __bfloat162float(h);
        __nv_bfloat16 l = __float2bfloat16(v - hf);
        int c = i >> 4, r = i & 15;
        int q = (r >> 1) & 3;
        int e = (r & 1) + ((r >> 3) << 1);
        size_t base = (((size_t)c * 4 + q) * KOUT + n) * 8;
        g_SB[base + e]     = h;
        g_SB[base + 4 + e] = l;

        unsigned long long key =
            ((unsigned long long)__float_as_uint(v) << 32) |
            (unsigned long long)(0x7FFFFFFFu - (unsigned)i);
        if (key > c3) {
            if (key > c0)      { c3 = c2; c2 = c1; c1 = c0; c0 = key; }
            else if (key > c1) { c3 = c2; c2 = c1; c1 = key; }
            else if (key > c2) { c3 = c2; c2 = key; }
            else                 c3 = key;
        }
    }
    __syncthreads();

    /* top-64: shfl argmax over 256 cache heads; winner pops / rescans */
    for (int t = 0; t < KOUT; t++) {
        unsigned long long v = c0;
#pragma unroll
        for (int off = 16; off; off >>= 1) {
            unsigned long long o = __shfl_xor_sync(0xffffffffu, v, off);
            if (o > v) v = o;
        }
        if (lane == 0) wbest[wid] = v;
        __syncthreads();
        if (wid == 0) {
            unsigned long long b = (lane < 8) ? wbest[lane] : 0ull;
#pragma unroll
            for (int off = 4; off; off >>= 1) {
                unsigned long long o = __shfl_xor_sync(0xffffffffu, b, off);
                if (o > b) b = o;
            }
            if (lane == 0) sbest = b;
        }
        __syncthreads();
        unsigned long long best = sbest;
        if (c0 == best) {   /* keys are unique -> exactly one winner */
            int col = (int)(0x7FFFFFFFu - (unsigned)(best & 0xFFFFFFFFull));
            g_candV[n * KOUT + t] = __uint_as_float((unsigned)(best >> 32));
            g_candC[n * KOUT + t] = col;
            row[col] = -1.0f;
            c0 = c1; c1 = c2; c2 = c3; c3 = 0;
            if (c0 == 0ull) {   /* cache exhausted: rebuild from own slice */
                for (int i = tid; i < D_DIM; i += 256) {
                    float vv = row[i];
                    if (vv > 0.f) {
                        unsigned long long key =
                            ((unsigned long long)__float_as_uint(vv) << 32) |
                            (unsigned long long)(0x7FFFFFFFu - (unsigned)i);
                        if (key > c3) {
                            if (key > c0)      { c3 = c2; c2 = c1; c1 = c0; c0 = key; }
                            else if (key > c1) { c3 = c2; c2 = c1; c1 = key; }
                            else if (key > c2) { c3 = c2; c2 = key; }
                            else                 c3 = key;
                        }
                    }
                }
            }
        }
        __syncthreads();
    }
}

/* -------- kernel C: greedy bipartite on 64x64 cands (1 warp, shfl only) ----- */
__global__ void kC_greedy() {
    __shared__ float cv[KOUT * KOUT];
    __shared__ int   cc[KOUT * KOUT];
    __shared__ unsigned used[(D_DIM + 31) / 32];

    int lane = threadIdx.x;  /* 32 threads */
    for (int i = lane; i < KOUT * KOUT; i += 32) { cv[i] = g_candV[i]; cc[i] = g_candC[i]; }
    for (int i = lane; i < (D_DIM + 31) / 32; i += 32) used[i] = 0u;
    __syncwarp();

    int r0 = lane, r1 = lane + 32;
    int p0 = 0, p1 = 0;
    bool d0 = false, d1 = false;

    for (int t = 0; t < KOUT; t++) {
        unsigned long long k0 = 0ull, k1 = 0ull;
        int col0 = -1, col1 = -1;
        if (!d0) {
            while (p0 < KOUT) {
                int c = cc[r0 * KOUT + p0];
                if ((used[c >> 5] >> (c & 31)) & 1u) p0++;
                else { col0 = c; break; }
            }
            if (col0 >= 0)
                k0 = ((unsigned long long)__float_as_uint(cv[r0 * KOUT + p0]) << 32) |
                     (unsigned long long)(0x7FFFFFFFu - (unsigned)(r0 * D_DIM + col0));
        }
        if (!d1) {
            while (p1 < KOUT) {
                int c = cc[r1 * KOUT + p1];
                if ((used[c >> 5] >> (c & 31)) & 1u) p1++;
                else { col1 = c; break; }
            }
            if (col1 >= 0)
                k1 = ((unsigned long long)__float_as_uint(cv[r1 * KOUT + p1]) << 32) |
                     (unsigned long long)(0x7FFFFFFFu - (unsigned)(r1 * D_DIM + col1));
        }
        unsigned long long m = k0 > k1 ? k0 : k1;
#pragma unroll
        for (int off = 16; off; off >>= 1) {
            unsigned long long o = __shfl_xor_sync(0xffffffffu, m, off);
            if (o > m) m = o;
        }
        if (m != 0ull) {
            if (!d0 && k0 == m) {
                d0 = true; g_assign[r0] = col0;
                used[col0 >> 5] |= (1u << (col0 & 31));
            } else if (!d1 && k1 == m) {
                d1 = true; g_assign[r1] = col1;
                used[col1 >> 5] |= (1u << (col1 & 31));
            }
        }
        __syncwarp();
    }
}

/* ------------------------- discrete output kernels ------------------------- */
__global__ void kD_zero(float* out) {
    int i = blockIdx.x * blockDim.x + threadIdx.x;
    float4* p = reinterpret_cast<float4*>(out + DISC_OFF);
    if (i < (KOUT * D_DIM) / 4) p[i] = make_float4(0.f, 0.f, 0.f, 0.f);
}
__global__ void kD2_finalize(float* out, const float* __restrict__ temp) {
    int r = threadIdx.x;
    if (r < KOUT) out[DISC_OFF + r * D_DIM + g_assign[r]] = 1.0f;
    if (r == 0)  out[TEMP_OFF] = fmaxf(0.1f, temp[0] * 0.99999f);
}

/* ------------------------------ GEMM (split-K) ----------------------------- */
__device__ __forceinline__ void cvt_hilo(float a, float b, unsigned &hi, unsigned &lo) {
    __nv_bfloat16 ha = __float2bfloat16(a);
    __nv_bfloat16 hb = __float2bfloat16(b);
    float fa = __bfloat162float(ha), fb = __bfloat162float(hb);
    __nv_bfloat16 la = __float2bfloat16(a - fa);
    __nv_bfloat16 lb = __float2bfloat16(b - fb);
    hi = ((unsigned)__bfloat16_as_ushort(hb) << 16) | (unsigned)__bfloat16_as_ushort(ha);
    lo = ((unsigned)__bfloat16_as_ushort(lb) << 16) | (unsigned)__bfloat16_as_ushort(la);
}

__device__ __forceinline__ void mma_bf16(float* c, unsigned a0, unsigned a1,
                                         unsigned a2, unsigned a3,
                                         unsigned b0, unsigned b1) {
    asm volatile(
        "mma.sync.aligned.m16n8k16.row.col.f32.bf16.bf16.f32 "
        "{%0,%1,%2,%3}, {%4,%5,%6,%7}, {%8,%9}, {%0,%1,%2,%3};\n"
        : "+f"(c[0]), "+f"(c[1]), "+f"(c[2]), "+f"(c[3])
        : "r"(a0), "r"(a1), "r"(a2), "r"(a3), "r"(b0), "r"(b1));
}

__global__ void __launch_bounds__(256, 2) kE_gemm(const float* __restrict__ X) {
    __shared__ __align__(16) __nv_bfloat16 sb[8 * 4 * KOUT * 8]; /* 32 KB */

    int mblk = blockIdx.x, seg = blockIdx.y;
    int tid = threadIdx.x, w = tid >> 5, lane = tid & 31;
    int tq = lane & 3, tg = lane >> 2;
    int r0 = mblk * 128 + w * 16 + tg;

    float acc[8][4];
#pragma unroll
    for (int j = 0; j < 8; j++) { acc[j][0] = acc[j][1] = acc[j][2] = acc[j][3] = 0.f; }

    const int chunk0 = seg * CPS;
    for (int t = 0; t < CPS; t += 8) {
        int nch = min(8, CPS - t);
        /* stage packed S tile: contiguous nch*4KB */
        {
            const uint4* gsrc = reinterpret_cast<const uint4*>(g_SB) +
                                (size_t)(chunk0 + t) * 256;
            uint4* sdst = reinterpret_cast<uint4*>(sb);
            int nvec = nch * 256;
            for (int i = tid; i < nvec; i += 256) sdst[i] = gsrc[i];
        }
        __syncthreads();

        for (int cci = 0; cci < nch; cci++) {
            int kg = (chunk0 + t + cci) * 16 + tq * 2;
            const float* xp  = X + (size_t)r0 * D_DIM + kg;
            const float* xp1 = xp + (size_t)8 * D_DIM;
            float2 x00 = *reinterpret_cast<const float2*>(xp);
            float2 x01 = *reinterpret_cast<const float2*>(xp + 8);
            float2 x10 = *reinterpret_cast<const float2*>(xp1);
            float2 x11 = *reinterpret_cast<const float2*>(xp1 + 8);

            unsigned a0h, a0l, a1h, a1l, a2h, a2l, a3h, a3l;
            cvt_hilo(x00.x, x00.y, a0h, a0l);
            cvt_hilo(x10.x, x10.y, a1h, a1l);
            cvt_hilo(x01.x, x01.y, a2h, a2l);
            cvt_hilo(x11.x, x11.y, a3h, a3l);

            /* load all 8 B fragments first, then 3 passes of 8 independent mmas */
            const uint4* bp = reinterpret_cast<const uint4*>(sb) +
                              (cci * 4 + tq) * KOUT + tg;
            unsigned bx[8], by[8], bz[8], bw[8];
#pragma unroll
            for (int j = 0; j < 8; j++) {
                uint4 bv = bp[j * 8];
                bx[j] = bv.x; by[j] = bv.y; bz[j] = bv.z; bw[j] = bv.w;
            }
#pragma unroll
            for (int j = 0; j < 8; j++)
                mma_bf16(acc[j], a0h, a1h, a2h, a3h, bx[j], by[j]); /* Xhi*Shi */
#pragma unroll
            for (int j = 0; j < 8; j++)
                mma_bf16(acc[j], a0h, a1h, a2h, a3h, bz[j], bw[j]); /* Xhi*Slo */
#pragma unroll
            for (int j = 0; j < 8; j++)
                mma_bf16(acc[j], a0l, a1l, a2l, a3l, bx[j], by[j]); /* Xlo*Shi */
        }
        __syncthreads();
    }

    float* pb = g_part + ((size_t)seg * BATCH + r0) * KOUT;
#pragma unroll
    for (int j = 0; j < 8; j++) {
        int c0 = j * 8 + tq * 2;
        pb[c0]              = acc[j][0];
        pb[c0 + 1]          = acc[j][1];
        pb[8 * KOUT + c0]     = acc[j][2];
        pb[8 * KOUT + c0 + 1] = acc[j][3];
    }
}

__global__ void kF_reduce(float* out) {
    int i = blockIdx.x * blockDim.x + threadIdx.x;
    if (i < BATCH * KOUT) {
        float s = 0.f;
#pragma unroll
        for (int t = 0; t < KSPLIT; t++) s += g_part[(size_t)t * BATCH * KOUT + i];
        out[Y_OFF + i] = s;
    }
}

/* --------------------------------- launcher -------------------------------- */
extern "C" void kernel_launch(void* const* d_in, const int* in_sizes, int n_in,
                              void* d_out, int out_size) {
    const float* X    = (const float*)d_in[0];
    const float* u    = (const float*)d_in[1];
    const float* tw   = (const float*)d_in[2];
    const float* temp = (const float*)d_in[3];
    float* out = (float*)d_out;

    cudaFuncSetAttribute(kB_rowsoftmax,
                         cudaFuncAttributeMaxDynamicSharedMemorySize, 81920);

    /* order chosen so launch index 3 (what ncu captures) is the GEMM */
    kA1_denom<<<(D_DIM * 32 + 255) / 256, 256>>>(u, tw);
    kA2_compute_w<<<(KOUT * D_DIM + 255) / 256, 256>>>(u, tw, temp);
    kB_rowsoftmax<<<KOUT, 256, D_DIM * sizeof(float)>>>();
    kE_gemm<<<dim3(BATCH / 128, KSPLIT), 256>>>(X);
    kC_greedy<<<1, 32>>>();
    kD_zero<<<(KOUT * D_DIM / 4 + 255) / 256, 256>>>(out);
    kD2_finalize<<<1, KOUT>>>(out, temp);
    kF_reduce<<<(BATCH * KOUT + 255) / 256, 256>>>(out);
}

// round 17
// speedup vs baseline: 1.9125x; 1.9125x over previous
#include <cuda_runtime.h>
#include <cuda_bf16.h>
#include <cstdint>

#define D_DIM   20000
#define KOUT    64
#define BATCH   4096
#define BINS    10
#define NCHUNK  1250            /* D_DIM / 16 */
#define KSPLIT  10
#define CPS     125             /* chunks per K segment (125*16 = 2000) */

#define Y_OFF   0
#define DISC_OFF (BATCH * KOUT)            /* 262144 */
#define TEMP_OFF (DISC_OFF + KOUT * D_DIM) /* 1542144 */

/* ------------------------- scratch (device globals) ------------------------- */
__device__ float          g_W[KOUT * D_DIM];                 /* (logits+gumbel)/t  */
__device__ float          g_max[D_DIM];
__device__ float          g_logden[D_DIM];
__device__ __nv_bfloat16  g_SB[(size_t)NCHUNK * 4 * KOUT * 8]; /* packed S hi/lo   */
__device__ float          g_candV[KOUT * KOUT];
__device__ int            g_candC[KOUT * KOUT];
__device__ int            g_assign[KOUT];
__device__ float          g_part[(size_t)KSPLIT * BATCH * KOUT];

/* ------------------------------- threefry ---------------------------------- */
/* JAX threefry2x32 with key = threefry_seed(42) = (0, 42). */
__device__ __forceinline__ void threefry2x32(unsigned c0, unsigned c1,
                                             unsigned &o0, unsigned &o1) {
    const unsigned k0 = 0u, k1 = 42u, k2 = 0x1BD11BF0u; /* 0x1BD11BDA^0^42 */
    unsigned x0 = c0 + k0, x1 = c1 + k1;
#define TFR(r) { x0 += x1; x1 = (x1 << r) | (x1 >> (32 - r)); x1 ^= x0; }
    TFR(13) TFR(15) TFR(26) TFR(6)   x0 += k1; x1 += k2 + 1u;
    TFR(17) TFR(29) TFR(16) TFR(24)  x0 += k2; x1 += k0 + 2u;
    TFR(13) TFR(15) TFR(26) TFR(6)   x0 += k0; x1 += k1 + 3u;
    TFR(17) TFR(29) TFR(16) TFR(24)  x0 += k1; x1 += k2 + 4u;
    TFR(13) TFR(15) TFR(26) TFR(6)   x0 += k2; x1 += k0 + 5u;
#undef TFR
    o0 = x0; o1 = x1;
}

/* jax_threefry_partitionable 32-bit path: counter (0, i), bits = o0 ^ o1. */
__device__ __forceinline__ float gumbel_at(unsigned flat) {
    unsigned o0, o1;
    threefry2x32(0u, flat, o0, o1);
    unsigned bits = o0 ^ o1;
    float f   = __uint_as_float((bits >> 9) | 0x3f800000u) - 1.0f; /* [0,1) */
    float val = f * (1.0f - 1e-7f) + 1e-7f;
    val = fmaxf(1e-7f, val);
    return -logf(-logf(val));
}

/* ------- kernel A1: per-d softmax max & log-denominator (warp per d) -------- */
__global__ void kA1_denom(const float* __restrict__ u,
                          const float* __restrict__ tw) {
    __shared__ float stw[BINS * KOUT];
    int tid = threadIdx.x;
    for (int i = tid; i < BINS * KOUT; i += blockDim.x) stw[i] = tw[i];
    __syncthreads();

    int gw = (blockIdx.x * blockDim.x + tid) >> 5;
    int lane = tid & 31;
    if (gw >= D_DIM) return;
    int d = gw;

    float uv[BINS];
#pragma unroll
    for (int j = 0; j < BINS; j++) uv[j] = u[(size_t)d * BINS + j];

    float d0 = 0.f, d1 = 0.f;
#pragma unroll
    for (int j = 0; j < BINS; j++) {
        d0 += uv[j] * stw[j * KOUT + lane];
        d1 += uv[j] * stw[j * KOUT + lane + 32];
    }
    float m = fmaxf(d0, d1);
#pragma unroll
    for (int off = 16; off; off >>= 1) m = fmaxf(m, __shfl_xor_sync(0xffffffffu, m, off));
    float s = expf(d0 - m) + expf(d1 - m);
#pragma unroll
    for (int off = 16; off; off >>= 1) s += __shfl_xor_sync(0xffffffffu, s, off);
    if (lane == 0) { g_max[d] = m; g_logden[d] = logf(s); }
}

/* ---------- kernel A2: W[k][d] = (log(10*clip(al)) + gumbel)/t -------------
   log(10*clip(al)) = log(10) + clamp(dot - m - logden, log(eps), log(1-1e-7)) */
__global__ void kA2_compute_w(const float* __restrict__ u,
                              const float* __restrict__ tw,
                              const float* __restrict__ temp) {
    int idx = blockIdx.x * blockDim.x + threadIdx.x;
    if (idx >= KOUT * D_DIM) return;
    int k = idx / D_DIM;
    int d = idx - k * D_DIM;

    float dot = 0.f;
#pragma unroll
    for (int j = 0; j < BINS; j++)
        dot += u[(size_t)d * BINS + j] * __ldg(&tw[j * KOUT + k]);

    float t = dot - g_max[d] - g_logden[d];             /* = log(al) */
    t = fminf(fmaxf(t, -16.11809565f), -1.0000000e-7f); /* log clip  */
    float lg = 2.302585093f + t;                        /* log(10*al)*/
    float g  = gumbel_at((unsigned)idx);                /* flat = k*D+d */
    float nt = fmaxf(0.1f, temp[0] * 0.99999f);
    g_W[idx] = (lg + g) / nt;
}

/* ------- kernel B: row softmax + packed bf16 hi/lo S + per-row top-64 ------- */
__global__ void kB_rowsoftmax() {
    extern __shared__ float row[];             /* 20000 floats = 80000 B */
    __shared__ float red[256];
    __shared__ unsigned long long wbest[8];
    __shared__ unsigned long long sbest;

    int n = blockIdx.x, tid = threadIdx.x;
    int wid = tid >> 5, lane = tid & 31;
    const float* Wrow = g_W + (size_t)n * D_DIM;

    float m = -1e30f;
    for (int i = tid; i < D_DIM; i += 256) { float v = Wrow[i]; row[i] = v; m = fmaxf(m, v); }
    red[tid] = m; __syncthreads();
    for (int s = 128; s > 0; s >>= 1) { if (tid < s) red[tid] = fmaxf(red[tid], red[tid + s]); __syncthreads(); }
    m = red[0]; __syncthreads();

    float ps = 0.f;
    for (int i = tid; i < D_DIM; i += 256) { float e = expf(row[i] - m); row[i] = e; ps += e; }
    red[tid] = ps; __syncthreads();
    for (int s = 128; s > 0; s >>= 1) { if (tid < s) red[tid] += red[tid + s]; __syncthreads(); }
    float inv = 1.0f / red[0]; __syncthreads();

    /* normalize + pack hi/lo bf16 (mma B-fragment order) + build top-4 cache */
    unsigned long long c0 = 0, c1 = 0, c2 = 0, c3 = 0;
    for (int i = tid; i < D_DIM; i += 256) {
        float v = row[i] * inv;
        row[i] = v;
        __nv_bfloat16 h = __float2bfloat16(v);
        float hf = __bfloat162float(h);
        __nv_bfloat16 l = __float2bfloat16(v - hf);
        int c = i >> 4, r = i & 15;
        int q = (r >> 1) & 3;
        int e = (r & 1) + ((r >> 3) << 1);
        size_t base = (((size_t)c * 4 + q) * KOUT + n) * 8;
        g_SB[base + e]     = h;
        g_SB[base + 4 + e] = l;

        unsigned long long key =
            ((unsigned long long)__float_as_uint(v) << 32) |
            (unsigned long long)(0x7FFFFFFFu - (unsigned)i);
        if (key > c3) {
            if (key > c0)      { c3 = c2; c2 = c1; c1 = c0; c0 = key; }
            else if (key > c1) { c3 = c2; c2 = c1; c1 = key; }
            else if (key > c2) { c3 = c2; c2 = key; }
            else                 c3 = key;
        }
    }
    __syncthreads();

    /* top-64: shfl argmax over 256 cache heads; winner pops / rescans */
    for (int t = 0; t < KOUT; t++) {
        unsigned long long v = c0;
#pragma unroll
        for (int off = 16; off; off >>= 1) {
            unsigned long long o = __shfl_xor_sync(0xffffffffu, v, off);
            if (o > v) v = o;
        }
        if (lane == 0) wbest[wid] = v;
        __syncthreads();
        if (wid == 0) {
            unsigned long long b = (lane < 8) ? wbest[lane] : 0ull;
#pragma unroll
            for (int off = 4; off; off >>= 1) {
                unsigned long long o = __shfl_xor_sync(0xffffffffu, b, off);
                if (o > b) b = o;
            }
            if (lane == 0) sbest = b;
        }
        __syncthreads();
        unsigned long long best = sbest;
        if (c0 == best) {   /* keys are unique -> exactly one winner */
            int col = (int)(0x7FFFFFFFu - (unsigned)(best & 0xFFFFFFFFull));
            g_candV[n * KOUT + t] = __uint_as_float((unsigned)(best >> 32));
            g_candC[n * KOUT + t] = col;
            row[col] = -1.0f;
            c0 = c1; c1 = c2; c2 = c3; c3 = 0;
            if (c0 == 0ull) {   /* cache exhausted: rebuild from own slice */
                for (int i = tid; i < D_DIM; i += 256) {
                    float vv = row[i];
                    if (vv > 0.f) {
                        unsigned long long key =
                            ((unsigned long long)__float_as_uint(vv) << 32) |
                            (unsigned long long)(0x7FFFFFFFu - (unsigned)i);
                        if (key > c3) {
                            if (key > c0)      { c3 = c2; c2 = c1; c1 = c0; c0 = key; }
                            else if (key > c1) { c3 = c2; c2 = c1; c1 = key; }
                            else if (key > c2) { c3 = c2; c2 = key; }
                            else                 c3 = key;
                        }
                    }
                }
            }
        }
        __syncthreads();
    }
}

/* -------- kernel C: greedy bipartite on 64x64 cands (1 warp, shfl only) ----- */
__global__ void kC_greedy() {
    __shared__ float cv[KOUT * KOUT];
    __shared__ int   cc[KOUT * KOUT];
    __shared__ unsigned used[(D_DIM + 31) / 32];

    int lane = threadIdx.x;  /* 32 threads */
    for (int i = lane; i < KOUT * KOUT; i += 32) { cv[i] = g_candV[i]; cc[i] = g_candC[i]; }
    for (int i = lane; i < (D_DIM + 31) / 32; i += 32) used[i] = 0u;
    __syncwarp();

    int r0 = lane, r1 = lane + 32;
    int p0 = 0, p1 = 0;
    bool d0 = false, d1 = false;

    for (int t = 0; t < KOUT; t++) {
        unsigned long long k0 = 0ull, k1 = 0ull;
        int col0 = -1, col1 = -1;
        if (!d0) {
            while (p0 < KOUT) {
                int c = cc[r0 * KOUT + p0];
                if ((used[c >> 5] >> (c & 31)) & 1u) p0++;
                else { col0 = c; break; }
            }
            if (col0 >= 0)
                k0 = ((unsigned long long)__float_as_uint(cv[r0 * KOUT + p0]) << 32) |
                     (unsigned long long)(0x7FFFFFFFu - (unsigned)(r0 * D_DIM + col0));
        }
        if (!d1) {
            while (p1 < KOUT) {
                int c = cc[r1 * KOUT + p1];
                if ((used[c >> 5] >> (c & 31)) & 1u) p1++;
                else { col1 = c; break; }
            }
            if (col1 >= 0)
                k1 = ((unsigned long long)__float_as_uint(cv[r1 * KOUT + p1]) << 32) |
                     (unsigned long long)(0x7FFFFFFFu - (unsigned)(r1 * D_DIM + col1));
        }
        unsigned long long m = k0 > k1 ? k0 : k1;
#pragma unroll
        for (int off = 16; off; off >>= 1) {
            unsigned long long o = __shfl_xor_sync(0xffffffffu, m, off);
            if (o > m) m = o;
        }
        if (m != 0ull) {
            if (!d0 && k0 == m) {
                d0 = true; g_assign[r0] = col0;
                used[col0 >> 5] |= (1u << (col0 & 31));
            } else if (!d1 && k1 == m) {
                d1 = true; g_assign[r1] = col1;
                used[col1 >> 5] |= (1u << (col1 & 31));
            }
        }
        __syncwarp();
    }
}

/* ------------------------- discrete output kernels ------------------------- */
__global__ void kD_zero(float* out) {
    int i = blockIdx.x * blockDim.x + threadIdx.x;
    float4* p = reinterpret_cast<float4*>(out + DISC_OFF);
    if (i < (KOUT * D_DIM) / 4) p[i] = make_float4(0.f, 0.f, 0.f, 0.f);
}
__global__ void kD2_finalize(float* out, const float* __restrict__ temp) {
    int r = threadIdx.x;
    if (r < KOUT) out[DISC_OFF + r * D_DIM + g_assign[r]] = 1.0f;
    if (r == 0)  out[TEMP_OFF] = fmaxf(0.1f, temp[0] * 0.99999f);
}

/* ------------------------------ GEMM (split-K) ----------------------------- */
__device__ __forceinline__ void cvt_hilo(float a, float b, unsigned &hi, unsigned &lo) {
    __nv_bfloat16 ha = __float2bfloat16(a);
    __nv_bfloat16 hb = __float2bfloat16(b);
    float fa = __bfloat162float(ha), fb = __bfloat162float(hb);
    __nv_bfloat16 la = __float2bfloat16(a - fa);
    __nv_bfloat16 lb = __float2bfloat16(b - fb);
    hi = ((unsigned)__bfloat16_as_ushort(hb) << 16) | (unsigned)__bfloat16_as_ushort(ha);
    lo = ((unsigned)__bfloat16_as_ushort(lb) << 16) | (unsigned)__bfloat16_as_ushort(la);
}

__device__ __forceinline__ void mma_bf16(float* c, unsigned a0, unsigned a1,
                                         unsigned a2, unsigned a3,
                                         unsigned b0, unsigned b1) {
    asm volatile(
        "mma.sync.aligned.m16n8k16.row.col.f32.bf16.bf16.f32 "
        "{%0,%1,%2,%3}, {%4,%5,%6,%7}, {%8,%9}, {%0,%1,%2,%3};\n"
        : "+f"(c[0]), "+f"(c[1]), "+f"(c[2]), "+f"(c[3])
        : "r"(a0), "r"(a1), "r"(a2), "r"(a3), "r"(b0), "r"(b1));
}

/* smem B tile is XOR-swizzled: uint4 index i stores element i of the linear
   layout at i ^ (((i>>6)&3)<<1)  (i.e. n' = n ^ (tq<<1)).  This makes the
   LDS.128 bank-group = tg ^ (tq<<1), a distinct permutation per tq ->
   conflict-free (4 cyc) instead of 4-way conflicted (16 cyc). */
__global__ void __launch_bounds__(256, 3) kE_gemm(const float* __restrict__ X) {
    __shared__ __align__(16) __nv_bfloat16 sb[8 * 4 * KOUT * 8]; /* 32 KB */

    int mblk = blockIdx.x, seg = blockIdx.y;
    int tid = threadIdx.x, w = tid >> 5, lane = tid & 31;
    int tq = lane & 3, tg = lane >> 2;
    int r0 = mblk * 128 + w * 16 + tg;

    float acc[8][4];
#pragma unroll
    for (int j = 0; j < 8; j++) { acc[j][0] = acc[j][1] = acc[j][2] = acc[j][3] = 0.f; }

    const int chunk0 = seg * CPS;
    for (int t = 0; t < CPS; t += 8) {
        int nch = min(8, CPS - t);
        /* stage packed S tile (swizzled store): contiguous nch*4KB */
        {
            const uint4* gsrc = reinterpret_cast<const uint4*>(g_SB) +
                                (size_t)(chunk0 + t) * 256;
            uint4* sdst = reinterpret_cast<uint4*>(sb);
            int nvec = nch * 256;
            for (int i = tid; i < nvec; i += 256)
                sdst[i ^ (((i >> 6) & 3) << 1)] = gsrc[i];
        }
        __syncthreads();

#pragma unroll 2
        for (int cci = 0; cci < nch; cci++) {
            int kg = (chunk0 + t + cci) * 16 + tq * 2;
            const float* xp  = X + (size_t)r0 * D_DIM + kg;
            const float* xp1 = xp + (size_t)8 * D_DIM;
            float2 x00 = *reinterpret_cast<const float2*>(xp);
            float2 x01 = *reinterpret_cast<const float2*>(xp + 8);
            float2 x10 = *reinterpret_cast<const float2*>(xp1);
            float2 x11 = *reinterpret_cast<const float2*>(xp1 + 8);

            unsigned a0h, a0l, a1h, a1l, a2h, a2l, a3h, a3l;
            cvt_hilo(x00.x, x00.y, a0h, a0l);
            cvt_hilo(x10.x, x10.y, a1h, a1l);
            cvt_hilo(x01.x, x01.y, a2h, a2l);
            cvt_hilo(x11.x, x11.y, a3h, a3l);

            const uint4* bp = reinterpret_cast<const uint4*>(sb) +
                              (cci * 4 + tq) * KOUT + (tg ^ (tq << 1));
#pragma unroll
            for (int j = 0; j < 8; j++) {
                uint4 bv = bp[j * 8];
                mma_bf16(acc[j], a0h, a1h, a2h, a3h, bv.x, bv.y); /* Xhi*Shi */
                mma_bf16(acc[j], a0h, a1h, a2h, a3h, bv.z, bv.w); /* Xhi*Slo */
                mma_bf16(acc[j], a0l, a1l, a2l, a3l, bv.x, bv.y); /* Xlo*Shi */
            }
        }
        __syncthreads();
    }

    float* pb = g_part + ((size_t)seg * BATCH + r0) * KOUT;
#pragma unroll
    for (int j = 0; j < 8; j++) {
        int c0 = j * 8 + tq * 2;
        pb[c0]              = acc[j][0];
        pb[c0 + 1]          = acc[j][1];
        pb[8 * KOUT + c0]     = acc[j][2];
        pb[8 * KOUT + c0 + 1] = acc[j][3];
    }
}

__global__ void kF_reduce(float* out) {
    int i = blockIdx.x * blockDim.x + threadIdx.x;
    if (i < BATCH * KOUT) {
        float s = 0.f;
#pragma unroll
        for (int t = 0; t < KSPLIT; t++) s += g_part[(size_t)t * BATCH * KOUT + i];
        out[Y_OFF + i] = s;
    }
}

/* --------------------------------- launcher -------------------------------- */
extern "C" void kernel_launch(void* const* d_in, const int* in_sizes, int n_in,
                              void* d_out, int out_size) {
    const float* X    = (const float*)d_in[0];
    const float* u    = (const float*)d_in[1];
    const float* tw   = (const float*)d_in[2];
    const float* temp = (const float*)d_in[3];
    float* out = (float*)d_out;

    cudaFuncSetAttribute(kB_rowsoftmax,
                         cudaFuncAttributeMaxDynamicSharedMemorySize, 81920);

    /* order chosen so launch index 3 (what ncu captures) is the GEMM */
    kA1_denom<<<(D_DIM * 32 + 255) / 256, 256>>>(u, tw);
    kA2_compute_w<<<(KOUT * D_DIM + 255) / 256, 256>>>(u, tw, temp);
    kB_rowsoftmax<<<KOUT, 256, D_DIM * sizeof(float)>>>();
    kE_gemm<<<dim3(BATCH / 128, KSPLIT), 256>>>(X);
    kC_greedy<<<1, 32>>>();
    kD_zero<<<(KOUT * D_DIM / 4 + 255) / 256, 256>>>(out);
    kD2_finalize<<<1, KOUT>>>(out, temp);
    kF_reduce<<<(BATCH * KOUT + 255) / 256, 256>>>(out);
}